// round 3
// baseline (speedup 1.0000x reference)
#include <cuda_runtime.h>

// ModifiedLogicSegLoss: loss = sum_{b,c} w[c] * (softplus(x) - t*x)
//   w[c] = sum_l La[l,c]*lam[l] / 128   (levels partition classes; clamp never fires)
// B=262144, C=128 -> 2^23 float4 vectors per input array.
// Single fused kernel; hierarchical arrival counters avoid the serialized
// 1024-deep single-address atomic drain at block-finish time.

#define NBLOCKS   1024
#define NTHREADS  256
#define NC        128
#define NVEC      (1u << 23)                       // 8,388,608 float4 elements
#define ITERS     (NVEC / (NBLOCKS * NTHREADS))    // 32, compile-time
#define NGROUPS   64
#define GRPSZ     (NBLOCKS / NGROUPS)              // 16

__device__ float g_partials[NBLOCKS];
// Group counters spaced 128B apart -> distinct L2 atomic queues (parallel drain).
__device__ unsigned int g_done1[NGROUPS * 32];
__device__ unsigned int g_done2 = 0;

__device__ __forceinline__ float bce_elem(float x, float t) {
    // softplus(x) - t*x, stable form: max(x,0) + log1p(exp(-|x|))
    float e  = __expf(-fabsf(x));
    float sp = fmaxf(x, 0.0f) + __logf(1.0f + e);
    return fmaf(-t, x, sp);
}

__global__ void __launch_bounds__(NTHREADS)
loss_fused(const float4* __restrict__ yp, const float4* __restrict__ yt,
           const float*  __restrict__ La, const float*  __restrict__ lam,
           float* __restrict__ out) {
    __shared__ __align__(16) float w[NC];
    __shared__ float wred[NTHREADS / 32];
    __shared__ bool s_last;
    const int tid = threadIdx.x;

    // Build per-class weights once per block (La: [4,128], lam: [4])
    if (tid < NC) {
        float a = 0.0f;
        #pragma unroll
        for (int l = 0; l < 4; ++l)
            a = fmaf(La[l * NC + tid], lam[l], a);
        w[tid] = a * (1.0f / (float)NC);
    }
    __syncthreads();

    const unsigned gid = blockIdx.x * NTHREADS + tid;
    // Grid stride (2^18) is a multiple of 32 -> class-quad index is loop-invariant.
    const float4 wv = reinterpret_cast<const float4*>(w)[gid & 31];

    float acc = 0.0f;
    #pragma unroll 8
    for (int i = 0; i < ITERS; ++i) {
        const unsigned v = gid + (unsigned)i * (NBLOCKS * NTHREADS);
        const float4 x = yp[v];
        const float4 t = yt[v];
        float s =      wv.x * bce_elem(x.x, t.x);
        s = fmaf(wv.y, bce_elem(x.y, t.y), s);
        s = fmaf(wv.z, bce_elem(x.z, t.z), s);
        s = fmaf(wv.w, bce_elem(x.w, t.w), s);
        acc += s;
    }

    // Intra-block reduce: warp shfl, then warp 0 folds the 8 warp sums.
    #pragma unroll
    for (int o = 16; o > 0; o >>= 1)
        acc += __shfl_xor_sync(0xffffffffu, acc, o);
    if ((tid & 31) == 0) wred[tid >> 5] = acc;
    __syncthreads();

    if (tid < 32) {
        float a = (tid < NTHREADS / 32) ? wred[tid] : 0.0f;
        #pragma unroll
        for (int o = 4; o > 0; o >>= 1)
            a += __shfl_xor_sync(0xffffffffu, a, o);
        if (tid == 0) {
            g_partials[blockIdx.x] = a;
            __threadfence();
            // Two-level arrival: 16-deep drain per group counter (parallel
            // across 64 spaced counters), then 64-deep on the global counter.
            unsigned o1 = atomicAdd(&g_done1[(blockIdx.x & (NGROUPS - 1)) * 32], 1u);
            bool grp_last = (o1 == GRPSZ - 1);
            bool lst = false;
            if (grp_last) {
                unsigned o2 = atomicAdd(&g_done2, 1u);
                lst = (o2 == NGROUPS - 1);
            }
            s_last = lst;
        }
    }
    __syncthreads();

    // Last block performs the fixed-order final reduction (deterministic).
    if (s_last) {
        __shared__ float fin[NTHREADS / 32];
        // 1024 partials = 256 float4: one per thread, summed in fixed order.
        const float4 p = reinterpret_cast<const float4*>(g_partials)[tid];
        float a = ((p.x + p.y) + (p.z + p.w));
        #pragma unroll
        for (int o = 16; o > 0; o >>= 1)
            a += __shfl_xor_sync(0xffffffffu, a, o);
        if ((tid & 31) == 0) fin[tid >> 5] = a;

        // Re-arm counters for the next graph replay.
        if (tid < NGROUPS) g_done1[tid * 32] = 0u;
        if (tid == NGROUPS) g_done2 = 0u;
        __syncthreads();

        if (tid < 32) {
            float b = (tid < NTHREADS / 32) ? fin[tid] : 0.0f;
            #pragma unroll
            for (int o = 4; o > 0; o >>= 1)
                b += __shfl_xor_sync(0xffffffffu, b, o);
            if (tid == 0) out[0] = b;
        }
    }
}

extern "C" void kernel_launch(void* const* d_in, const int* in_sizes, int n_in,
                              void* d_out, int out_size) {
    (void)in_sizes; (void)n_in; (void)out_size;
    loss_fused<<<NBLOCKS, NTHREADS>>>(
        (const float4*)d_in[0], (const float4*)d_in[1],
        (const float*)d_in[2],  (const float*)d_in[3],
        (float*)d_out);
}

// round 4
// speedup vs baseline: 1.0228x; 1.0228x over previous
#include <cuda_runtime.h>

// ModifiedLogicSegLoss: loss = sum_{b,c} w[c] * (softplus(x) - t*x)
//   w[c] = sum_l La[l,c]*lam[l] / 128   (levels partition classes; clamp never fires)
// B=262144, C=128 -> 2^23 float4 vectors per input array.
// Single fused kernel. The block-completion protocol uses one acq_rel atomic
// (NO __threadfence: gpu-scope fence emits CCTL.IVALL = full L1D invalidate
// per block on sm_103a, which was costing ~5us of epilogue tail).

#define NBLOCKS   1024
#define NTHREADS  256
#define NC        128
#define NVEC      (1u << 23)                       // 8,388,608 float4 elements
#define ITERS     (NVEC / (NBLOCKS * NTHREADS))    // 32, compile-time

__device__ float g_partials[NBLOCKS];
__device__ unsigned int g_done = 0;                // re-armed by last block

__device__ __forceinline__ unsigned ticket_acq_rel(unsigned int* p) {
    unsigned old;
    asm volatile("atom.global.add.acq_rel.gpu.u32 %0, [%1], 1;"
                 : "=r"(old) : "l"(p) : "memory");
    return old;
}

__device__ __forceinline__ float bce_elem(float x, float t) {
    // softplus(x) - t*x, stable form: max(x,0) + log1p(exp(-|x|))
    float e  = __expf(-fabsf(x));
    float sp = fmaxf(x, 0.0f) + __logf(1.0f + e);
    return fmaf(-t, x, sp);
}

__global__ void __launch_bounds__(NTHREADS)
loss_fused(const float4* __restrict__ yp, const float4* __restrict__ yt,
           const float*  __restrict__ La, const float*  __restrict__ lam,
           float* __restrict__ out) {
    __shared__ __align__(16) float w[NC];
    __shared__ float wred[NTHREADS / 32];
    __shared__ bool s_last;
    const int tid = threadIdx.x;

    // Build per-class weights once per block (La: [4,128], lam: [4])
    if (tid < NC) {
        float a = 0.0f;
        #pragma unroll
        for (int l = 0; l < 4; ++l)
            a = fmaf(La[l * NC + tid], lam[l], a);
        w[tid] = a * (1.0f / (float)NC);
    }
    __syncthreads();

    const unsigned gid = blockIdx.x * NTHREADS + tid;
    // Grid stride (2^18) is a multiple of 32 -> class-quad index is loop-invariant.
    const float4 wv = reinterpret_cast<const float4*>(w)[gid & 31];

    float acc = 0.0f;
    #pragma unroll 8
    for (int i = 0; i < ITERS; ++i) {
        const unsigned v = gid + (unsigned)i * (NBLOCKS * NTHREADS);
        const float4 x = __ldcs(yp + v);           // streaming: evict-first
        const float4 t = __ldcs(yt + v);
        float s =      wv.x * bce_elem(x.x, t.x);
        s = fmaf(wv.y, bce_elem(x.y, t.y), s);
        s = fmaf(wv.z, bce_elem(x.z, t.z), s);
        s = fmaf(wv.w, bce_elem(x.w, t.w), s);
        acc += s;
    }

    // Intra-block reduce: warp shfl, then warp 0 folds the 8 warp sums.
    #pragma unroll
    for (int o = 16; o > 0; o >>= 1)
        acc += __shfl_xor_sync(0xffffffffu, acc, o);
    if ((tid & 31) == 0) wred[tid >> 5] = acc;
    __syncthreads();

    if (tid < 32) {
        float a = (tid < NTHREADS / 32) ? wred[tid] : 0.0f;
        #pragma unroll
        for (int o = 4; o > 0; o >>= 1)
            a += __shfl_xor_sync(0xffffffffu, a, o);
        if (tid == 0) {
            g_partials[blockIdx.x] = a;
            // acq_rel ticket: release orders the partial store before the
            // increment; the winner's acquire orders its reads after all
            // other blocks' releases. No fence, no L1D flush.
            unsigned old = ticket_acq_rel(&g_done);
            s_last = (old == NBLOCKS - 1);
        }
    }
    __syncthreads();

    // Last-arriving block performs the fixed-order final reduction.
    if (s_last) {
        __shared__ float fin[NTHREADS / 32];
        // 1024 partials = 256 float4: one per thread, fixed order, L1-bypass
        // (__ldcg) so we read L2-coherent values published by other SMs.
        const float4 p = __ldcg(reinterpret_cast<const float4*>(g_partials) + tid);
        float a = ((p.x + p.y) + (p.z + p.w));
        #pragma unroll
        for (int o = 16; o > 0; o >>= 1)
            a += __shfl_xor_sync(0xffffffffu, a, o);
        if ((tid & 31) == 0) fin[tid >> 5] = a;
        if (tid == 0) g_done = 0u;                 // re-arm for next replay
        __syncthreads();

        if (tid < 32) {
            float b = (tid < NTHREADS / 32) ? fin[tid] : 0.0f;
            #pragma unroll
            for (int o = 4; o > 0; o >>= 1)
                b += __shfl_xor_sync(0xffffffffu, b, o);
            if (tid == 0) out[0] = b;
        }
    }
}

extern "C" void kernel_launch(void* const* d_in, const int* in_sizes, int n_in,
                              void* d_out, int out_size) {
    (void)in_sizes; (void)n_in; (void)out_size;
    loss_fused<<<NBLOCKS, NTHREADS>>>(
        (const float4*)d_in[0], (const float4*)d_in[1],
        (const float*)d_in[2],  (const float*)d_in[3],
        (float*)d_out);
}